// round 17
// baseline (speedup 1.0000x reference)
#include <cuda_runtime.h>
#include <cstdint>

// Problem constants
//  H=8, KB=8 cells; OB=64, IB=64, K=9, L=9; ZD=64, PD=16, DH=128
//  out: [512, 512, 9, 9] fp32 = 21,233,664 elements

__device__ float g_hid[64 * 128];   // relu(x @ W1^T + b1)

// Packed f32x2 FMA (sm_103a)
#define FMA_F32X2(d, a, b, c) \
    asm("fma.rn.f32x2 %0, %1, %2, %3;" : "=l"(d) : "l"(a), "l"(b), "l"(c))

__device__ __forceinline__ uint32_t smem_u32(const void* p) {
    uint32_t a;
    asm("{ .reg .u64 t; cvta.to.shared.u64 t, %1; cvt.u32.u64 %0, t; }" : "=r"(a) : "l"(p));
    return a;
}
#define CP_ASYNC16(dst, src) \
    asm volatile("cp.async.cg.shared.global [%0], [%1], 16;" :: "r"(dst), "l"(src))
#define CP_COMMIT() asm volatile("cp.async.commit_group;" ::: "memory")
#define CP_WAIT1()  asm volatile("cp.async.wait_group 1;" ::: "memory")
#define CP_WAIT0()  asm volatile("cp.async.wait_group 0;" ::: "memory")

// ---------------------------------------------------------------------------
// Kernel 1: hid[r][j] = relu(b1[j] + sum_t x[r][t] * W1[j][t])
// ---------------------------------------------------------------------------
__global__ __launch_bounds__(128)
void hypernet_hid(const float* __restrict__ z_all,
                  const float* __restrict__ W1,
                  const float* __restrict__ b1,
                  const float* __restrict__ pde)
{
    __shared__ float xs[80];
    const int r = blockIdx.x;
    const int j = threadIdx.x;
    if (j < 64)       xs[j] = z_all[r * 64 + j];
    else if (j < 80)  xs[j] = pde[j - 64];
    __syncthreads();

    const float4* wp = (const float4*)(W1 + j * 80);
    float acc = b1[j];
#pragma unroll
    for (int t = 0; t < 20; ++t) {
        float4 w = wp[t];
        acc = fmaf(w.x, xs[4*t+0], acc);
        acc = fmaf(w.y, xs[4*t+1], acc);
        acc = fmaf(w.z, xs[4*t+2], acc);
        acc = fmaf(w.w, xs[4*t+3], acc);
    }
    g_hid[r * 128 + j] = fmaxf(acc, 0.0f);
}

// ---------------------------------------------------------------------------
// Kernel 2 (fused): 4-cell register tile GEMM (as R16) + register-resident
// epilogue with compile-time indices (replaces the conflicted-gather epilogue).
// grid 512: blockIdx.x = ob*8 + ibg
// block 128: GEMM mapping tid = cg*8 + ibl; epilogue mapping tid = cell*2 + half
//
// smem pool (floats), dynamic, 54,528 B (4 blocks/SM, one wave of 512):
//   hs  [64][132] @0, wb0[72][36] @8448, wb1[72][36] @11040
//   epilogue aliases: exe_s[64][72] @0, un_s[64][72] @4608
// ---------------------------------------------------------------------------
__global__ __launch_bounds__(128, 4)
void fused_weight_gen(const float* __restrict__ W2,
                      const float* __restrict__ b2,
                      const float* __restrict__ unet,
                      float* __restrict__ out)
{
    extern __shared__ float sm[];
    float* hs    = sm;               // [64][132]
    float* wb0   = sm + 8448;        // [72][36]
    float* wb1   = sm + 11040;       // [72][36]
    float* exe_s = sm;               // [64][72] alias
    float* un_s  = sm + 4608;        // [64][72] alias

    const int tid    = threadIdx.x;
    const int ob     = blockIdx.x >> 3;
    const int ibg    = blockIdx.x & 7;
    const int ibbase = ibg * 8;
    const int base9  = (ob * 64 + ibbase) * 9;   // 72 contiguous W2 rows

    const int cg  = tid >> 3;   // cells cg*4 .. cg*4+3
    const int ibl = tid & 7;

    const uint32_t hs_u  = smem_u32(hs);
    const uint32_t wb0_u = smem_u32(wb0);
    const uint32_t wb1_u = smem_u32(wb1);

    // ---- prologue: async hid (ALL K=128: 32 float4/cell) + W2 chunk0 -> group0
    for (int idx = tid; idx < 2048; idx += 128) {
        int c = idx >> 5, q = idx & 31;
        CP_ASYNC16(hs_u + (uint32_t)(c * 132 + 4 * q) * 4u,
                   (const void*)(g_hid + c * 128 + 4 * q));
    }
    for (int idx = tid; idx < 576; idx += 128) {
        int row = idx >> 3, q = idx & 7;
        CP_ASYNC16(wb0_u + (uint32_t)(row * 36 + 4 * q) * 4u,
                   (const void*)(W2 + (size_t)(base9 + row) * 128 + 4 * q));
    }
    CP_COMMIT();
    // chunk1 -> group1
    for (int idx = tid; idx < 576; idx += 128) {
        int row = idx >> 3, q = idx & 7;
        CP_ASYNC16(wb1_u + (uint32_t)(row * 36 + 4 * q) * 4u,
                   (const void*)(W2 + (size_t)(base9 + row) * 128 + 32 + 4 * q));
    }
    CP_COMMIT();

    unsigned long long acc[4][9];
#pragma unroll
    for (int j = 0; j < 4; ++j)
#pragma unroll
        for (int k = 0; k < 9; ++k) acc[j][k] = 0ull;

    CP_WAIT1();          // group0 done: hs + chunk0 resident
    __syncthreads();

    const float* hp0 = hs + (cg * 4) * 132;
    const float* hp1 = hp0 + 132;
    const float* hp2 = hp0 + 264;
    const float* hp3 = hp0 + 396;

    // ---- GEMM: 4 chunks of 32 d, double buffered ----
#pragma unroll 1
    for (int c = 0; c < 4; ++c) {
        const float* wp = ((c & 1) ? wb1 : wb0) + ibl * 324;
        const int cb = c * 32;
#pragma unroll
        for (int dd = 0; dd < 32; dd += 4) {
            ulonglong2 h0 = *(const ulonglong2*)(hp0 + cb + dd);
            ulonglong2 h1 = *(const ulonglong2*)(hp1 + cb + dd);
            ulonglong2 h2 = *(const ulonglong2*)(hp2 + cb + dd);
            ulonglong2 h3 = *(const ulonglong2*)(hp3 + cb + dd);
#pragma unroll
            for (int k = 0; k < 9; ++k) {
                ulonglong2 w = *(const ulonglong2*)(wp + k * 36 + dd);
                FMA_F32X2(acc[0][k], h0.x, w.x, acc[0][k]);
                FMA_F32X2(acc[0][k], h0.y, w.y, acc[0][k]);
                FMA_F32X2(acc[1][k], h1.x, w.x, acc[1][k]);
                FMA_F32X2(acc[1][k], h1.y, w.y, acc[1][k]);
                FMA_F32X2(acc[2][k], h2.x, w.x, acc[2][k]);
                FMA_F32X2(acc[2][k], h2.y, w.y, acc[2][k]);
                FMA_F32X2(acc[3][k], h3.x, w.x, acc[3][k]);
                FMA_F32X2(acc[3][k], h3.y, w.y, acc[3][k]);
            }
        }
        __syncthreads();
        if (c < 2) {
            uint32_t bu = (c & 1) ? wb1_u : wb0_u;
            const float* src = W2 + (c + 2) * 32;
            for (int idx = tid; idx < 576; idx += 128) {
                int row = idx >> 3, q = idx & 7;
                CP_ASYNC16(bu + (uint32_t)(row * 36 + 4 * q) * 4u,
                           (const void*)(src + (size_t)(base9 + row) * 128 + 4 * q));
            }
            CP_COMMIT();
            CP_WAIT1();
        } else if (c == 2) {
            CP_WAIT0();
        }
        if (c < 3) __syncthreads();
    }
    __syncthreads();   // protect exe_s/un_s aliases over hs/wb

    // ---- finalize exe into smem ----
#pragma unroll
    for (int k = 0; k < 9; ++k) {
        float bvk = b2[base9 + ibl * 9 + k];
#pragma unroll
        for (int j = 0; j < 4; ++j) {
            float2 p = *(float2*)&acc[j][k];
            exe_s[(cg * 4 + j) * 72 + ibl * 9 + k] = p.x + p.y + bvk;
        }
    }

    // ---- stage unet: per cell 72 contiguous floats = 18 float4 ----
    for (int idx = tid; idx < 1152; idx += 128) {
        int cell = idx / 18, q = idx - cell * 18;
        int h = cell >> 3, kb = cell & 7;
        size_t bu = ((size_t)(h * 64 + ob) * 512 + (size_t)(kb * 64 + ibbase)) * 9;
        *(float4*)(un_s + cell * 72 + 4 * q) = *(const float4*)(unet + bu + 4 * q);
    }
    __syncthreads();

    // ---- epilogue: register-resident e/u, compile-time product indices ----
    // thread -> (cell = tid>>1, half = tid&1): owns 4 ib rows = 324 contiguous
    // out floats (16B aligned). 18 conflict-free LDS.128, then 81 unrolled
    // STG.128 with constant register indices. Zero per-iteration ALU/LDS.
    {
        const int cell = tid >> 1;
        const int half = tid & 1;
        const float* es = exe_s + cell * 72 + half * 36;
        const float* us = un_s  + cell * 72 + half * 36;

        float e[36], u[36];
#pragma unroll
        for (int i = 0; i < 9; ++i) {
            *(float4*)(e + 4 * i) = *(const float4*)(es + 4 * i);
            *(float4*)(u + 4 * i) = *(const float4*)(us + 4 * i);
        }

        const int h  = cell >> 3;
        const int kb = cell & 7;
        float* op = out +
            ((size_t)(h * 64 + ob) * 512 + (size_t)(kb * 64 + ibbase)) * 81 +
            half * 324;

#pragma unroll
        for (int f = 0; f < 81; ++f) {
            float4 v;
            {   const int p = 4 * f + 0;
                v.x = e[p / 9] * u[(p / 81) * 9 + (p % 9)]; }
            {   const int p = 4 * f + 1;
                v.y = e[p / 9] * u[(p / 81) * 9 + (p % 9)]; }
            {   const int p = 4 * f + 2;
                v.z = e[p / 9] * u[(p / 81) * 9 + (p % 9)]; }
            {   const int p = 4 * f + 3;
                v.w = e[p / 9] * u[(p / 81) * 9 + (p % 9)]; }
            *(float4*)(op + 4 * f) = v;
        }
    }
}

// ---------------------------------------------------------------------------
extern "C" void kernel_launch(void* const* d_in, const int* in_sizes, int n_in,
                              void* d_out, int out_size)
{
    const float* z_all = (const float*)d_in[0];   // [64, 64]
    const float* W1    = (const float*)d_in[1];   // [128, 80]
    const float* b1    = (const float*)d_in[2];   // [128]
    const float* W2    = (const float*)d_in[3];   // [36864, 128]
    const float* b2    = (const float*)d_in[4];   // [36864]
    const float* unet  = (const float*)d_in[5];   // [512, 512, 9]
    const float* pde   = (const float*)d_in[6];   // [16]
    float* out = (float*)d_out;                   // [512, 512, 9, 9]

    cudaFuncSetAttribute(fused_weight_gen,
                         cudaFuncAttributeMaxDynamicSharedMemorySize, 54528);

    hypernet_hid<<<64, 128>>>(z_all, W1, b1, pde);
    fused_weight_gen<<<512, 128, 54528>>>(W2, b2, unet, out);
}